// round 1
// baseline (speedup 1.0000x reference)
#include <cuda_runtime.h>
#include <math.h>

// Shapes: x[B=1024][T=8][V=4][D=8] float32.  Series (v,t): rows b at x + t*32 + v*8 + b*256.
// M = 1024 - HIST_K(4) = 1020 points per TE problem. 28 pairs p=(v,t>=1), tgt series = (v,0).
#define B_N   1024
#define M_N   1020
#define RS    1024      // row stride for all matrices
#define N_SER 32
#define N_PAIR 28

// Scratch (static __device__ arrays -- allocation-free per harness rules)
__device__ float g_E  [N_SER  * B_N * RS];   // 8-dim Chebyshev distance matrices (134 MB)
__device__ float g_WB [N_PAIR * M_N * RS];   // dB(i,j) = max_{r<4} E[v,t][i+r][j+r]
__device__ float g_WC [4      * M_N * RS];   // dC(i,j) from E[v,0]
__device__ float g_WAC[4      * M_N * RS];   // dAC = max(dC, E[v,0][i+4][j+4])
__device__ float g_part[N_PAIR * 128];
__device__ float g_psi[1040];

// ---------------- digamma table: psi[k] for integer k, built each launch (deterministic) ----
__global__ void psi_kernel() {
    int k = blockIdx.x * blockDim.x + threadIdx.x;
    if (k >= 1040) return;
    if (k == 0) { g_psi[0] = 0.f; return; }
    double s = 0.0;
    #pragma unroll
    for (int m = 0; m < 8; m++) s += 1.0 / (double)(k + m);   // shift recurrence
    double y = (double)k + 8.0;
    double inv = 1.0 / y, inv2 = inv * inv;
    double ps = log(y) - 0.5 * inv
              - inv2 * (1.0 / 12.0 - inv2 * (1.0 / 120.0 - inv2 * (1.0 / 252.0)));
    g_psi[k] = (float)(ps - s);
}

// ---------------- E[s][i][j] = max_d |x_s[i][d] - x_s[j][d]|  (full 1024x1024) -------------
__global__ void e_kernel(const float* __restrict__ x) {
    __shared__ float xs[B_N * 12];            // row stride 12 floats: 16B-aligned, 4-way-min banks
    int s = blockIdx.y;
    int v = s >> 3, t = s & 7;
    const float* base = x + t * 32 + v * 8;
    for (int idx = threadIdx.x; idx < B_N * 8; idx += blockDim.x) {
        int b = idx >> 3, d = idx & 7;
        xs[b * 12 + d] = base[b * 256 + d];
    }
    __syncthreads();
    int warp = threadIdx.x >> 5, lane = threadIdx.x & 31;
    float* Eo = g_E + (size_t)s * (B_N * RS);
    for (int iw = 0; iw < 8; iw++) {
        int i = blockIdx.x * 64 + iw * 8 + warp;
        float4 xa = *(const float4*)&xs[i * 12];
        float4 xb = *(const float4*)&xs[i * 12 + 4];
        float* orow = Eo + (size_t)i * RS;
        for (int it = 0; it < 8; it++) {
            int j4 = it * 128 + lane * 4;
            float res[4];
            #pragma unroll
            for (int c = 0; c < 4; c++) {
                int j = j4 + c;
                float4 ya = *(const float4*)&xs[j * 12];
                float4 yb = *(const float4*)&xs[j * 12 + 4];
                float m;
                m =          fabsf(xa.x - ya.x);
                m = fmaxf(m, fabsf(xa.y - ya.y));
                m = fmaxf(m, fabsf(xa.z - ya.z));
                m = fmaxf(m, fabsf(xa.w - ya.w));
                m = fmaxf(m, fabsf(xb.x - yb.x));
                m = fmaxf(m, fabsf(xb.y - yb.y));
                m = fmaxf(m, fabsf(xb.z - yb.z));
                m = fmaxf(m, fabsf(xb.w - yb.w));
                res[c] = m;
            }
            *(float4*)(orow + j4) = make_float4(res[0], res[1], res[2], res[3]);
        }
    }
}

// ---------------- diagonal 4-window max: WB / (WC + WAC) ------------------------------------
__global__ void w_kernel() {
    int m = blockIdx.y;
    int warp = threadIdx.x >> 5, lane = threadIdx.x & 31;
    int i = blockIdx.x * 8 + warp;
    if (i >= M_N) return;
    const float* E;
    float *outB = 0, *outC = 0, *outAC = 0;
    if (m < N_PAIR) {
        int v = m / 7, t = 1 + m % 7;
        E    = g_E  + (size_t)(v * 8 + t) * (B_N * RS);
        outB = g_WB + (size_t)m * (M_N * RS) + (size_t)i * RS;
    } else {
        int v = m - N_PAIR;
        E     = g_E   + (size_t)(v * 8) * (B_N * RS);
        outC  = g_WC  + (size_t)v * (M_N * RS) + (size_t)i * RS;
        outAC = g_WAC + (size_t)v * (M_N * RS) + (size_t)i * RS;
    }
    for (int it = 0; it < 8; it++) {
        int j4 = it * 128 + lane * 4;
        if (j4 >= M_N) continue;
        float o[4] = {-1e30f, -1e30f, -1e30f, -1e30f};
        #pragma unroll
        for (int r = 0; r < 4; r++) {
            const float* row = E + (size_t)(i + r) * RS + j4;
            float e8[8];
            float4 qa = *(const float4*)row;
            e8[0] = qa.x; e8[1] = qa.y; e8[2] = qa.z; e8[3] = qa.w;
            if (r > 0) {   // window r+c <= 6; r=0 touches only e8[0..3]
                float4 qb = *(const float4*)(row + 4);
                e8[4] = qb.x; e8[5] = qb.y; e8[6] = qb.z; e8[7] = qb.w;
            }
            #pragma unroll
            for (int c = 0; c < 4; c++)
                o[c] = fmaxf(o[c], e8[r + c]);
        }
        if (outB) {
            *(float4*)(outB + j4) = make_float4(o[0], o[1], o[2], o[3]);
        } else {
            *(float4*)(outC + j4) = make_float4(o[0], o[1], o[2], o[3]);
            float4 qa4 = *(const float4*)(E + (size_t)(i + 4) * RS + j4 + 4); // E[i+4][j4+4+c]
            *(float4*)(outAC + j4) = make_float4(
                fmaxf(o[0], qa4.x), fmaxf(o[1], qa4.y),
                fmaxf(o[2], qa4.z), fmaxf(o[3], qa4.w));
        }
    }
}

// ---------------- per-row kNN(3) + counts; warp per row -------------------------------------
__device__ __forceinline__ void ins3(float v, float& t0, float& t1, float& t2) {
    if (v < t2) {
        if (v < t1) {
            t2 = t1;
            if (v < t0) { t1 = t0; t0 = v; } else t1 = v;
        } else t2 = v;
    }
}

__global__ void te_kernel() {
    int p = blockIdx.y;            // pair 0..27
    int v = p / 7;
    int warp = threadIdx.x >> 5, lane = threadIdx.x & 31;
    int i = blockIdx.x * 8 + warp;
    __shared__ float ws[8];
    float wrow = 0.f;
    if (i < M_N) {
        const float* wb  = g_WB  + (size_t)p * (M_N * RS) + (size_t)i * RS;
        const float* wac = g_WAC + (size_t)v * (M_N * RS) + (size_t)i * RS;
        const float* wc  = g_WC  + (size_t)v * (M_N * RS) + (size_t)i * RS;

        // pass 1: eps_i = 3rd smallest of dJ = max(WAC, WB), excluding j==i
        float t0 = 1e30f, t1 = 1e30f, t2 = 1e30f;
        for (int it = 0; it < 8; it++) {
            int j4 = it * 128 + lane * 4;
            if (j4 >= M_N) continue;
            float4 b4 = *(const float4*)(wb + j4);
            float4 a4 = *(const float4*)(wac + j4);
            const float* bb = (const float*)&b4;
            const float* aa = (const float*)&a4;
            #pragma unroll
            for (int c = 0; c < 4; c++) {
                int j = j4 + c;
                float dj = fmaxf(bb[c], aa[c]);
                if (j != i) ins3(dj, t0, t1, t2);
            }
        }
        #pragma unroll
        for (int off = 16; off > 0; off >>= 1) {     // butterfly top-3 merge
            float o0 = __shfl_xor_sync(0xffffffffu, t0, off);
            float o1 = __shfl_xor_sync(0xffffffffu, t1, off);
            float o2 = __shfl_xor_sync(0xffffffffu, t2, off);
            ins3(o0, t0, t1, t2); ins3(o1, t0, t1, t2); ins3(o2, t0, t1, t2);
        }
        float eps = t2;

        // pass 2: counts (strict <, exclude self); dBC = max(WB, WC)
        int nA = 0, nB = 0, nC = 0;
        for (int it = 0; it < 8; it++) {
            int j4 = it * 128 + lane * 4;
            if (j4 >= M_N) continue;
            float4 b4 = *(const float4*)(wb + j4);
            float4 a4 = *(const float4*)(wac + j4);
            float4 c4 = *(const float4*)(wc + j4);
            const float* bb = (const float*)&b4;
            const float* aa = (const float*)&a4;
            const float* cc = (const float*)&c4;
            #pragma unroll
            for (int c = 0; c < 4; c++) {
                int j = j4 + c;
                if (j == i) continue;
                float dc = cc[c];
                nC += (dc < eps);
                nA += (aa[c] < eps);
                nB += (fmaxf(bb[c], dc) < eps);
            }
        }
        #pragma unroll
        for (int off = 16; off > 0; off >>= 1) {
            nA += __shfl_xor_sync(0xffffffffu, nA, off);
            nB += __shfl_xor_sync(0xffffffffu, nB, off);
            nC += __shfl_xor_sync(0xffffffffu, nC, off);
        }
        wrow = g_psi[nC + 1] - g_psi[nA + 1] - g_psi[nB + 1];
    }
    if (lane == 0) ws[warp] = wrow;
    __syncthreads();
    if (threadIdx.x == 0) {
        float sum = 0.f;
        for (int k = 0; k < 8; k++) sum += ws[k];
        g_part[p * 128 + blockIdx.x] = sum;
    }
}

// ---------------- deterministic final reduction ---------------------------------------------
__global__ void reduce_kernel(float* __restrict__ out) {
    __shared__ float sm[256];
    float s = 0.f;
    for (int idx = threadIdx.x; idx < N_PAIR * 128; idx += 256) s += g_part[idx];
    sm[threadIdx.x] = s;
    __syncthreads();
    if (threadIdx.x == 0) {
        float tot = 0.f;
        for (int k = 0; k < 256; k++) tot += sm[k];
        float psi3  = g_psi[3];                   // digamma(KNN_K=3)
        float scale = 0.1f / 256.0f;              // BETA / (T*V*D)
        // result = scale * (1/V) * sum_p [ psi3 + (sum_i w)/M ]
        out[0] = scale * 0.25f * (28.0f * psi3 + tot / 1020.0f);
    }
}

extern "C" void kernel_launch(void* const* d_in, const int* in_sizes, int n_in,
                              void* d_out, int out_size) {
    const float* x = (const float*)d_in[0];
    float* out = (float*)d_out;
    psi_kernel   <<<5, 256>>>();
    e_kernel     <<<dim3(16, 32),  256>>>(x);
    w_kernel     <<<dim3(128, 32), 256>>>();
    te_kernel    <<<dim3(128, 28), 256>>>();
    reduce_kernel<<<1, 256>>>(out);
}